// round 15
// baseline (speedup 1.0000x reference)
#include <cuda_runtime.h>
#include <cuda_bf16.h>
#include <cstdint>

// ============================================================================
// RNNModel B=262144, F=5, T=4, H=128, L=5 — bf16 mma.sync split-precision v7.
// 3-term split (W=Wh+Wl, h=hh+hl; D = AhBh + AhBl + AlBh), ldmatrix fragment
// loads, 4 batch groups of 4 warps. v7 = v6 (proven 2158us, clean identity-
// offset cp.async copies) + copy/compute overlap:
//   - Wih(0) copy issued under prologue x-staging
//   - Whh(l) copy issued under the t=0 epilogue
//   - Wih(l+1) copy issued under the t=3 epilogue + bias load
// At most ONE copy in flight at any time; barrier count unchanged.
// ============================================================================

#define HDIM 128
#define TSEQ 4
#define MB   64
#define NT   512
#define NLAYER 5

#define HPW  68                  // padded row stride in u32 words (136 bf16, 272 B)
#define ROWB 272                 // bytes per padded row
#define W_HALF_BYTES 34816       // 128*272
#define H_TILE_BYTES 17408       // 64*272

// ---- SMEM byte offsets ----
#define OFF_H     0                       // 4t x (hi 17408 + lo 17408) = 139264
#define H_PAIR    34816
#define OFF_W     139264                  // Whi 34816 + Wlo 34816 = 69632
#define OFF_X     208896                  // 4t x (hi 2048 + lo 2048) = 16384
#define X_PAIR    4096
#define OFF_B2    225280                  // 128 fp32
#define OFF_WFC   225792                  // 128 fp32
#define OFF_SPART 226304                  // 256 fp32
#define SMEM_BYTES 227328

// ---- pre-split, PADDED weights (mirror of SMEM layout): slot 2l = W_ih(l),
// 2l+1 = W_hh(l). layout: [j][136] bf16 rows; cols >= real K zero-filled.
__device__ __align__(16) __nv_bfloat16 g_Whi[10][17408];
__device__ __align__(16) __nv_bfloat16 g_Wlo[10][17408];

__device__ __forceinline__ uint32_t smem_u32(const void* p){
    uint32_t a;
    asm("{ .reg .u64 t; cvta.to.shared.u64 t, %1; cvt.u32.u64 %0, t; }"
        : "=r"(a) : "l"(p));
    return a;
}

__device__ __forceinline__ void ldm4(uint32_t* r, uint32_t addr){
    asm volatile("ldmatrix.sync.aligned.m8n8.x4.shared.b16 {%0,%1,%2,%3}, [%4];"
        : "=r"(r[0]), "=r"(r[1]), "=r"(r[2]), "=r"(r[3]) : "r"(addr));
}

__device__ __forceinline__ void mma16816(float* c,
        uint32_t a0, uint32_t a1, uint32_t a2, uint32_t a3,
        uint32_t b0, uint32_t b1){
    asm volatile(
        "mma.sync.aligned.m16n8k16.row.col.f32.bf16.bf16.f32 "
        "{%0,%1,%2,%3}, {%4,%5,%6,%7}, {%8,%9}, {%0,%1,%2,%3};"
        : "+f"(c[0]), "+f"(c[1]), "+f"(c[2]), "+f"(c[3])
        : "r"(a0), "r"(a1), "r"(a2), "r"(a3), "r"(b0), "r"(b1));
}

#define GROUP_BAR(gid) \
    asm volatile("bar.sync %0, %1;" :: "r"((gid) + 1), "r"(128) : "memory")

__device__ __forceinline__ void cp_async16(uint32_t dst, const void* src){
    asm volatile("cp.async.cg.shared.global [%0], [%1], 16;"
                 :: "r"(dst), "l"(src) : "memory");
}
#define CP_ASYNC_COMMIT() asm volatile("cp.async.commit_group;" ::: "memory")
#define CP_ASYNC_WAIT()   asm volatile("cp.async.wait_group 0;" ::: "memory")

// accurate tanh (~1e-7 abs). NOT tanh.approx (6e-4 would compound over 20 steps).
__device__ __forceinline__ float fast_tanh(float x){
    float ax = fabsf(x);
    float e  = __expf(-2.0f * ax);
    float r  = __fdividef(1.0f - e, 1.0f + e);
    return copysignf(r, x);
}

// ============================================================================
// Prep: split all 10 weight matrices into bf16 hi/lo, padded [j][136] rows.
// ============================================================================
__global__ void prep_weights(const float* __restrict__ Wih0,
                             const float* __restrict__ Whh0,
                             const float* __restrict__ WihS,
                             const float* __restrict__ WhhS){
    int slot = blockIdx.x;
    for (int idx = threadIdx.x; idx < 17408; idx += blockDim.x){
        int j = idx / 136, k = idx % 136;
        float w = 0.0f;
        if (slot == 0)      { if (k < 5)   w = Wih0[j*5 + k]; }
        else if (slot == 1) { if (k < 128) w = Whh0[j*128 + k]; }
        else if (slot & 1)  { if (k < 128) w = WhhS[((slot>>1)-1)*16384 + j*128 + k]; }
        else                { if (k < 128) w = WihS[((slot>>1)-1)*16384 + j*128 + k]; }
        __nv_bfloat16 hi = __float2bfloat16(w);
        __nv_bfloat16 lo = __float2bfloat16(w - __bfloat162float(hi));
        g_Whi[slot][idx] = hi;
        g_Wlo[slot][idx] = lo;
    }
}

// async copy one matrix (hi+lo) into the SMEM W region — IDENTITY offsets
// (dst_off == src_off, 128B-sector aligned both sides -> full coalescing).
__device__ __forceinline__ void copyW_async(int slot, uint32_t sbW, int tid){
    const char* gh = (const char*)g_Whi[slot];
    const char* gl = (const char*)g_Wlo[slot];
    #pragma unroll 5
    for (int i = tid; i < 2176; i += NT){
        cp_async16(sbW + i*16,                 gh + i*16);
        cp_async16(sbW + W_HALF_BYTES + i*16,  gl + i*16);
    }
    CP_ASYNC_COMMIT();
}

// epilogue for one timestep: tanh, split hi/lo (packed cvt.rn — identical
// rounding to __float2bfloat16), store to h tiles
__device__ __forceinline__ void epi_store(const float* ct,
        uint32_t* hh, uint32_t* hl, int baseW){
    #pragma unroll
    for (int nf = 0; nf < 4; nf++){
        #pragma unroll
        for (int p = 0; p < 2; p++){
            float h0 = fast_tanh(ct[nf*4 + 2*p]);
            float h1 = fast_tanh(ct[nf*4 + 2*p + 1]);
            uint32_t ph;
            asm("cvt.rn.bf16x2.f32 %0, %1, %2;" : "=r"(ph) : "f"(h1), "f"(h0));
            float f0 = __uint_as_float(ph << 16);
            float f1 = __uint_as_float(ph & 0xffff0000u);
            uint32_t pl;
            asm("cvt.rn.bf16x2.f32 %0, %1, %2;" : "=r"(pl) : "f"(h1 - f1), "f"(h0 - f0));
            int widx = baseW + p*(8*HPW) + nf*4;
            hh[widx] = ph;
            hl[widx] = pl;
        }
    }
}

// ============================================================================
__global__ void __launch_bounds__(NT)
rnn_mma(const float* __restrict__ x,
        const float* __restrict__ bih0, const float* __restrict__ bhh0,
        const float* __restrict__ bihS, const float* __restrict__ bhhS,
        const float* __restrict__ Wfc,  const float* __restrict__ bfc,
        float* __restrict__ out, int Btot)
{
    extern __shared__ __align__(16) char smem[];
    const uint32_t sb = smem_u32(smem);
    const int tid  = threadIdx.x;
    const int wid  = tid >> 5, lane = tid & 31;
    const int g    = lane >> 2, c = lane & 3;
    const int grp  = wid >> 2;               // batch group 0..3 (spans all SMSPs)
    const int m0   = grp * 16;               // group's 16 batch rows
    const int n0   = (wid & 3) * 32;         // warp's hidden-col base
    const long long baseb = (long long)blockIdx.x * MB;

    float* b2  = (float*)(smem + OFF_B2);
    float* wfc = (float*)(smem + OFF_WFC);

    // ---- per-lane ldmatrix byte offsets ----
    const int aRow = m0 + (lane & 7) + ((lane >> 3) & 1) * 8;
    const int aK8  = (lane >> 4) * 8;
    const uint32_t aOff = (uint32_t)(aRow * ROWB + aK8 * 2);
    const int bRow = (lane & 7) + (lane >> 4) * 8;
    const int bK8  = ((lane >> 3) & 1) * 8;
    const uint32_t bOff0 = (uint32_t)((n0 + bRow) * ROWB + bK8 * 2);
    const uint32_t bOff1 = (uint32_t)((n0 + 16 + bRow) * ROWB + bK8 * 2);
    const int baseW = (m0 + g) * HPW + (n0 >> 1) + c;   // epilogue store base

    // ---- prologue: issue Wih(0) copy, then stage wfc + x beneath it ----
    copyW_async(0, sb + OFF_W, tid);

    if (tid < 128) wfc[tid] = Wfc[tid];
    if (tid < 256){
        int b = tid >> 2, t = tid & 3;
        long long gb = baseb + b;
        float xv[5];
        #pragma unroll
        for (int f = 0; f < 5; f++)
            xv[f] = (gb < Btot) ? x[gb*20 + f*4 + t] : 0.0f;
        uint32_t* xh = (uint32_t*)(smem + OFF_X + t*X_PAIR);
        uint32_t* xl = xh + 512;
        #pragma unroll
        for (int w = 0; w < 8; w++){
            float v0 = (2*w   < 5) ? xv[2*w]   : 0.0f;
            float v1 = (2*w+1 < 5) ? xv[2*w+1] : 0.0f;
            uint32_t ph;
            asm("cvt.rn.bf16x2.f32 %0, %1, %2;" : "=r"(ph) : "f"(v1), "f"(v0));
            float f0 = __uint_as_float(ph << 16);
            float f1 = __uint_as_float(ph & 0xffff0000u);
            uint32_t pl;
            asm("cvt.rn.bf16x2.f32 %0, %1, %2;" : "=r"(pl) : "f"(v1 - f1), "f"(v0 - f0));
            xh[b*8 + w] = ph;
            xl[b*8 + w] = pl;
        }
    }
    if (tid < 128) b2[tid] = bih0[tid] + bhh0[tid];      // layer-0 combined bias

    CP_ASYNC_WAIT();
    __syncthreads();

    float acc[64];                           // [t][nf][4]
    const uint32_t whAddr = sb + OFF_W;
    const uint32_t wlAddr = sb + OFF_W + W_HALF_BYTES;
    const uint32_t* whW = (const uint32_t*)(smem + OFF_W);
    const uint32_t* wlW = whW + (W_HALF_BYTES >> 2);

    #pragma unroll 1
    for (int l = 0; l < NLAYER; l++){
        // ---- init acc with bias (b2 holds layer-l combined bias) ----
        #pragma unroll
        for (int nf = 0; nf < 4; nf++){
            float bv0 = b2[n0 + nf*8 + c*2];
            float bv1 = b2[n0 + nf*8 + c*2 + 1];
            #pragma unroll
            for (int t = 0; t < 4; t++){
                float* cc = &acc[(t*4 + nf)*4];
                cc[0] = bv0; cc[1] = bv1; cc[2] = bv0; cc[3] = bv1;
            }
        }

        // ---- pass A: acc[t] += Wih . h_prev[t] (no barriers needed) ----
        if (l == 0){
            // single K=16 step from x tiles (scalar LDS; tiny)
            uint32_t bh[8], bl[8];
            #pragma unroll
            for (int nf = 0; nf < 4; nf++){
                int jw = (n0 + nf*8 + g)*HPW + c;
                bh[nf*2]   = whW[jw]; bh[nf*2+1] = whW[jw + 4];
                bl[nf*2]   = wlW[jw]; bl[nf*2+1] = wlW[jw + 4];
            }
            #pragma unroll
            for (int t = 0; t < 4; t++){
                const uint32_t* xh = (const uint32_t*)(smem + OFF_X + t*X_PAIR);
                const uint32_t* xl = xh + 512;
                int rw = (m0 + g)*8 + c;
                uint32_t ah0 = xh[rw], ah1 = xh[rw + 64];
                uint32_t ah2 = xh[rw + 4], ah3 = xh[rw + 68];
                uint32_t al0 = xl[rw], al1 = xl[rw + 64];
                uint32_t al2 = xl[rw + 4], al3 = xl[rw + 68];
                float* ct = &acc[t*16];
                #pragma unroll
                for (int nf = 0; nf < 4; nf++)
                    mma16816(ct + nf*4, ah0,ah1,ah2,ah3, bh[nf*2], bh[nf*2+1]);
                #pragma unroll
                for (int nf = 0; nf < 4; nf++)
                    mma16816(ct + nf*4, ah0,ah1,ah2,ah3, bl[nf*2], bl[nf*2+1]);
                #pragma unroll
                for (int nf = 0; nf < 4; nf++)
                    mma16816(ct + nf*4, al0,al1,al2,al3, bh[nf*2], bh[nf*2+1]);
            }
        } else {
            #pragma unroll 1
            for (int kk = 0; kk < 8; kk++){
                uint32_t kb = kk * 32;       // 16 bf16 = 32 bytes per k-chunk
                uint32_t bh[8], bl[8];
                ldm4(bh,     whAddr + bOff0 + kb);
                ldm4(bh + 4, whAddr + bOff1 + kb);
                ldm4(bl,     wlAddr + bOff0 + kb);
                ldm4(bl + 4, wlAddr + bOff1 + kb);
                #pragma unroll
                for (int t = 0; t < 4; t++){
                    uint32_t hAddr = sb + OFF_H + t*H_PAIR + aOff + kb;
                    uint32_t ah[4], al[4];
                    ldm4(ah, hAddr);
                    ldm4(al, hAddr + H_TILE_BYTES);
                    float* ct = &acc[t*16];
                    #pragma unroll
                    for (int nf = 0; nf < 4; nf++)
                        mma16816(ct + nf*4, ah[0],ah[1],ah[2],ah[3], bh[nf*2], bh[nf*2+1]);
                    #pragma unroll
                    for (int nf = 0; nf < 4; nf++)
                        mma16816(ct + nf*4, ah[0],ah[1],ah[2],ah[3], bl[nf*2], bl[nf*2+1]);
                    #pragma unroll
                    for (int nf = 0; nf < 4; nf++)
                        mma16816(ct + nf*4, al[0],al[1],al[2],al[3], bh[nf*2], bh[nf*2+1]);
                }
            }
        }

        // ---- Whh(l) copy overlapped with the t=0 epilogue ----
        __syncthreads();                     // all pass-A W reads done (CTA-wide)
        copyW_async(2*l + 1, sb + OFF_W, tid);
        {
            uint32_t* hh0 = (uint32_t*)(smem + OFF_H + 0*H_PAIR);
            epi_store(&acc[0], hh0, hh0 + (H_TILE_BYTES >> 2), baseW);
        }
        CP_ASYNC_WAIT();
        __syncthreads();                     // Whh ready; h[0] visible CTA-wide

        // ---- pass B: t = 1..3 chains (t=1,2 epilogues inline) ----
        #pragma unroll 1
        for (int t = 1; t < 4; t++){
            float* ct = &acc[t*16];
            uint32_t hBase = sb + OFF_H + (t-1)*H_PAIR;
            #pragma unroll 1
            for (int kk = 0; kk < 8; kk++){
                uint32_t kb = kk * 32;
                uint32_t bh[8], bl[8], ah[4], al[4];
                ldm4(bh,     whAddr + bOff0 + kb);
                ldm4(bh + 4, whAddr + bOff1 + kb);
                ldm4(bl,     wlAddr + bOff0 + kb);
                ldm4(bl + 4, wlAddr + bOff1 + kb);
                ldm4(ah, hBase + aOff + kb);
                ldm4(al, hBase + aOff + kb + H_TILE_BYTES);
                #pragma unroll
                for (int nf = 0; nf < 4; nf++)
                    mma16816(ct + nf*4, ah[0],ah[1],ah[2],ah[3], bh[nf*2], bh[nf*2+1]);
                #pragma unroll
                for (int nf = 0; nf < 4; nf++)
                    mma16816(ct + nf*4, ah[0],ah[1],ah[2],ah[3], bl[nf*2], bl[nf*2+1]);
                #pragma unroll
                for (int nf = 0; nf < 4; nf++)
                    mma16816(ct + nf*4, al[0],al[1],al[2],al[3], bh[nf*2], bh[nf*2+1]);
            }
            if (t < 3){
                uint32_t* hh = (uint32_t*)(smem + OFF_H + t*H_PAIR);
                epi_store(ct, hh, hh + (H_TILE_BYTES >> 2), baseW);
                GROUP_BAR(grp);              // h[t] visible within this batch group
            }
        }

        // ---- Wih(l+1) copy overlapped with the t=3 epilogue + bias load ----
        __syncthreads();                     // all groups' t=3 W reads done
        if (l < NLAYER-1){
            copyW_async(2*l + 2, sb + OFF_W, tid);
            if (tid < 128)
                b2[tid] = bihS[l*128 + tid] + bhhS[l*128 + tid];  // layer l+1 bias
        }
        {
            uint32_t* hh3 = (uint32_t*)(smem + OFF_H + 3*H_PAIR);
            epi_store(&acc[48], hh3, hh3 + (H_TILE_BYTES >> 2), baseW);
        }
        if (l < NLAYER-1){
            CP_ASYNC_WAIT();
            __syncthreads();                 // Wih ready; h[3] + b2 visible
        }
    }

    __syncthreads();                         // all groups' h[3] complete (last layer)

    // ---- head: out[b] = dot(h3[b], wfc) + bfc ----
    if (tid < 256){
        int b = tid >> 2, q = tid & 3;
        const uint32_t* hh = (const uint32_t*)(smem + OFF_H + 3*H_PAIR);
        const uint32_t* hl = hh + (H_TILE_BYTES >> 2);
        float s = 0.0f;
        #pragma unroll
        for (int w = 0; w < 16; w++){
            int widx = b*HPW + q*16 + w;
            uint32_t uh = hh[widx], ul = hl[widx];
            __nv_bfloat162 vh = *(__nv_bfloat162*)&uh;
            __nv_bfloat162 vl = *(__nv_bfloat162*)&ul;
            int j = q*32 + 2*w;
            s = fmaf(__bfloat162float(vh.x) + __bfloat162float(vl.x), wfc[j],   s);
            s = fmaf(__bfloat162float(vh.y) + __bfloat162float(vl.y), wfc[j+1], s);
        }
        ((float*)(smem + OFF_SPART))[tid] = s;
    }
    __syncthreads();
    if (tid < 64){
        const float* sp = (const float*)(smem + OFF_SPART);
        long long gb = baseb + tid;
        if (gb < Btot)
            out[gb] = sp[tid*4] + sp[tid*4+1] + sp[tid*4+2] + sp[tid*4+3] + bfc[0];
    }
}

// ============================================================================
extern "C" void kernel_launch(void* const* d_in, const int* in_sizes, int n_in,
                              void* d_out, int out_size)
{
    const float* x    = (const float*)d_in[0];
    const float* Wih0 = (const float*)d_in[1];
    const float* Whh0 = (const float*)d_in[2];
    const float* bih0 = (const float*)d_in[3];
    const float* bhh0 = (const float*)d_in[4];
    const float* WihS = (const float*)d_in[5];
    const float* WhhS = (const float*)d_in[6];
    const float* bihS = (const float*)d_in[7];
    const float* bhhS = (const float*)d_in[8];
    const float* Wfc  = (const float*)d_in[9];
    const float* bfc  = (const float*)d_in[10];
    float* out = (float*)d_out;

    int Btot = in_sizes[0] / 20;
    int grid = (Btot + MB - 1) / MB;

    cudaFuncSetAttribute(rnn_mma,
                         cudaFuncAttributeMaxDynamicSharedMemorySize, SMEM_BYTES);

    prep_weights<<<10, 256>>>(Wih0, Whh0, WihS, WhhS);
    rnn_mma<<<grid, NT, SMEM_BYTES>>>(x, bih0, bhh0, bihS, bhhS,
                                      Wfc, bfc, out, Btot);
}

// round 16
// speedup vs baseline: 2.5617x; 2.5617x over previous
#include <cuda_runtime.h>
#include <cuda_bf16.h>
#include <cstdint>

// ============================================================================
// RNNModel B=262144, F=5, T=4, H=128, L=5 — bf16 mma.sync split-precision v8.
// 3-term split (W=Wh+Wl, h=hh+hl; D = AhBh + AhBl + AlBh), ldmatrix fragment
// loads, 4 batch groups of 4 warps. v8 = v6 (proven 2158us) with ONE minimal
// diff: the mid-layer CP_ASYNC_WAIT+sync moved inside the pass-B t-loop (at
// t==1), so the t=0 epilogue overlaps the Whh copy. epi_store call sites and
// acc indexing are unchanged (v4/v5/v7 regressions traced to register spills
// from restructured epilogues at the 128-reg/512-thread cap).
// ============================================================================

#define HDIM 128
#define TSEQ 4
#define MB   64
#define NT   512
#define NLAYER 5

#define HPW  68                  // padded row stride in u32 words (136 bf16, 272 B)
#define ROWB 272                 // bytes per padded row
#define W_HALF_BYTES 34816       // 128*272
#define H_TILE_BYTES 17408       // 64*272

// ---- SMEM byte offsets ----
#define OFF_H     0                       // 4t x (hi 17408 + lo 17408) = 139264
#define H_PAIR    34816
#define OFF_W     139264                  // Whi 34816 + Wlo 34816 = 69632
#define OFF_X     208896                  // 4t x (hi 2048 + lo 2048) = 16384
#define X_PAIR    4096
#define OFF_B2    225280                  // 128 fp32
#define OFF_WFC   225792                  // 128 fp32
#define OFF_SPART 226304                  // 256 fp32
#define SMEM_BYTES 227328

// ---- pre-split, PADDED weights (mirror of SMEM layout): slot 2l = W_ih(l),
// 2l+1 = W_hh(l). layout: [j][136] bf16 rows; cols >= real K zero-filled.
__device__ __align__(16) __nv_bfloat16 g_Whi[10][17408];
__device__ __align__(16) __nv_bfloat16 g_Wlo[10][17408];

__device__ __forceinline__ uint32_t smem_u32(const void* p){
    uint32_t a;
    asm("{ .reg .u64 t; cvta.to.shared.u64 t, %1; cvt.u32.u64 %0, t; }"
        : "=r"(a) : "l"(p));
    return a;
}

__device__ __forceinline__ void ldm4(uint32_t* r, uint32_t addr){
    asm volatile("ldmatrix.sync.aligned.m8n8.x4.shared.b16 {%0,%1,%2,%3}, [%4];"
        : "=r"(r[0]), "=r"(r[1]), "=r"(r[2]), "=r"(r[3]) : "r"(addr));
}

__device__ __forceinline__ void mma16816(float* c,
        uint32_t a0, uint32_t a1, uint32_t a2, uint32_t a3,
        uint32_t b0, uint32_t b1){
    asm volatile(
        "mma.sync.aligned.m16n8k16.row.col.f32.bf16.bf16.f32 "
        "{%0,%1,%2,%3}, {%4,%5,%6,%7}, {%8,%9}, {%0,%1,%2,%3};"
        : "+f"(c[0]), "+f"(c[1]), "+f"(c[2]), "+f"(c[3])
        : "r"(a0), "r"(a1), "r"(a2), "r"(a3), "r"(b0), "r"(b1));
}

#define GROUP_BAR(gid) \
    asm volatile("bar.sync %0, %1;" :: "r"((gid) + 1), "r"(128) : "memory")

__device__ __forceinline__ void cp_async16(uint32_t dst, const void* src){
    asm volatile("cp.async.cg.shared.global [%0], [%1], 16;"
                 :: "r"(dst), "l"(src) : "memory");
}
#define CP_ASYNC_COMMIT() asm volatile("cp.async.commit_group;" ::: "memory")
#define CP_ASYNC_WAIT()   asm volatile("cp.async.wait_group 0;" ::: "memory")

// accurate tanh (~1e-7 abs). NOT tanh.approx (6e-4 would compound over 20 steps).
__device__ __forceinline__ float fast_tanh(float x){
    float ax = fabsf(x);
    float e  = __expf(-2.0f * ax);
    float r  = __fdividef(1.0f - e, 1.0f + e);
    return copysignf(r, x);
}

// ============================================================================
// Prep: split all 10 weight matrices into bf16 hi/lo, padded [j][136] rows.
// ============================================================================
__global__ void prep_weights(const float* __restrict__ Wih0,
                             const float* __restrict__ Whh0,
                             const float* __restrict__ WihS,
                             const float* __restrict__ WhhS){
    int slot = blockIdx.x;
    for (int idx = threadIdx.x; idx < 17408; idx += blockDim.x){
        int j = idx / 136, k = idx % 136;
        float w = 0.0f;
        if (slot == 0)      { if (k < 5)   w = Wih0[j*5 + k]; }
        else if (slot == 1) { if (k < 128) w = Whh0[j*128 + k]; }
        else if (slot & 1)  { if (k < 128) w = WhhS[((slot>>1)-1)*16384 + j*128 + k]; }
        else                { if (k < 128) w = WihS[((slot>>1)-1)*16384 + j*128 + k]; }
        __nv_bfloat16 hi = __float2bfloat16(w);
        __nv_bfloat16 lo = __float2bfloat16(w - __bfloat162float(hi));
        g_Whi[slot][idx] = hi;
        g_Wlo[slot][idx] = lo;
    }
}

// async copy one matrix (hi+lo) into the SMEM W region — IDENTITY offsets
// (dst_off == src_off, 128B-sector aligned both sides -> full coalescing).
__device__ __forceinline__ void copyW_async(int slot, uint32_t sbW, int tid){
    const char* gh = (const char*)g_Whi[slot];
    const char* gl = (const char*)g_Wlo[slot];
    #pragma unroll 5
    for (int i = tid; i < 2176; i += NT){
        cp_async16(sbW + i*16,                 gh + i*16);
        cp_async16(sbW + W_HALF_BYTES + i*16,  gl + i*16);
    }
    CP_ASYNC_COMMIT();
}

// epilogue for one timestep: tanh, split hi/lo (packed cvt.rn — identical
// rounding to __float2bfloat16), store to h tiles
__device__ __forceinline__ void epi_store(const float* ct,
        uint32_t* hh, uint32_t* hl, int baseW){
    #pragma unroll
    for (int nf = 0; nf < 4; nf++){
        #pragma unroll
        for (int p = 0; p < 2; p++){
            float h0 = fast_tanh(ct[nf*4 + 2*p]);
            float h1 = fast_tanh(ct[nf*4 + 2*p + 1]);
            uint32_t ph;
            asm("cvt.rn.bf16x2.f32 %0, %1, %2;" : "=r"(ph) : "f"(h1), "f"(h0));
            float f0 = __uint_as_float(ph << 16);
            float f1 = __uint_as_float(ph & 0xffff0000u);
            uint32_t pl;
            asm("cvt.rn.bf16x2.f32 %0, %1, %2;" : "=r"(pl) : "f"(h1 - f1), "f"(h0 - f0));
            int widx = baseW + p*(8*HPW) + nf*4;
            hh[widx] = ph;
            hl[widx] = pl;
        }
    }
}

// ============================================================================
__global__ void __launch_bounds__(NT)
rnn_mma(const float* __restrict__ x,
        const float* __restrict__ bih0, const float* __restrict__ bhh0,
        const float* __restrict__ bihS, const float* __restrict__ bhhS,
        const float* __restrict__ Wfc,  const float* __restrict__ bfc,
        float* __restrict__ out, int Btot)
{
    extern __shared__ __align__(16) char smem[];
    const uint32_t sb = smem_u32(smem);
    const int tid  = threadIdx.x;
    const int wid  = tid >> 5, lane = tid & 31;
    const int g    = lane >> 2, c = lane & 3;
    const int grp  = wid >> 2;               // batch group 0..3 (spans all SMSPs)
    const int m0   = grp * 16;               // group's 16 batch rows
    const int n0   = (wid & 3) * 32;         // warp's hidden-col base
    const long long baseb = (long long)blockIdx.x * MB;

    float* b2  = (float*)(smem + OFF_B2);
    float* wfc = (float*)(smem + OFF_WFC);

    // ---- per-lane ldmatrix byte offsets ----
    const int aRow = m0 + (lane & 7) + ((lane >> 3) & 1) * 8;
    const int aK8  = (lane >> 4) * 8;
    const uint32_t aOff = (uint32_t)(aRow * ROWB + aK8 * 2);
    const int bRow = (lane & 7) + (lane >> 4) * 8;
    const int bK8  = ((lane >> 3) & 1) * 8;
    const uint32_t bOff0 = (uint32_t)((n0 + bRow) * ROWB + bK8 * 2);
    const uint32_t bOff1 = (uint32_t)((n0 + 16 + bRow) * ROWB + bK8 * 2);
    const int baseW = (m0 + g) * HPW + (n0 >> 1) + c;   // epilogue store base

    // ---- stage wfc + x tiles (bf16 hi/lo split, [64][8 words]) ----
    if (tid < 128) wfc[tid] = Wfc[tid];
    if (tid < 256){
        int b = tid >> 2, t = tid & 3;
        long long gb = baseb + b;
        float xv[5];
        #pragma unroll
        for (int f = 0; f < 5; f++)
            xv[f] = (gb < Btot) ? x[gb*20 + f*4 + t] : 0.0f;
        uint32_t* xh = (uint32_t*)(smem + OFF_X + t*X_PAIR);
        uint32_t* xl = xh + 512;
        #pragma unroll
        for (int w = 0; w < 8; w++){
            float v0 = (2*w   < 5) ? xv[2*w]   : 0.0f;
            float v1 = (2*w+1 < 5) ? xv[2*w+1] : 0.0f;
            uint32_t ph;
            asm("cvt.rn.bf16x2.f32 %0, %1, %2;" : "=r"(ph) : "f"(v1), "f"(v0));
            float f0 = __uint_as_float(ph << 16);
            float f1 = __uint_as_float(ph & 0xffff0000u);
            uint32_t pl;
            asm("cvt.rn.bf16x2.f32 %0, %1, %2;" : "=r"(pl) : "f"(v1 - f1), "f"(v0 - f0));
            xh[b*8 + w] = ph;
            xl[b*8 + w] = pl;
        }
    }

    float acc[64];                           // [t][nf][4]
    const uint32_t whAddr = sb + OFF_W;
    const uint32_t wlAddr = sb + OFF_W + W_HALF_BYTES;
    const uint32_t* whW = (const uint32_t*)(smem + OFF_W);
    const uint32_t* wlW = whW + (W_HALF_BYTES >> 2);

    #pragma unroll 1
    for (int l = 0; l < NLAYER; l++){
        __syncthreads();                     // all reads of previous W done
        copyW_async(2*l, sb + OFF_W, tid);
        if (tid < 128)
            b2[tid] = (l == 0) ? bih0[tid] + bhh0[tid]
                               : bihS[(l-1)*128 + tid] + bhhS[(l-1)*128 + tid];
        CP_ASYNC_WAIT();
        __syncthreads();

        // ---- init acc with bias ----
        #pragma unroll
        for (int nf = 0; nf < 4; nf++){
            float bv0 = b2[n0 + nf*8 + c*2];
            float bv1 = b2[n0 + nf*8 + c*2 + 1];
            #pragma unroll
            for (int t = 0; t < 4; t++){
                float* cc = &acc[(t*4 + nf)*4];
                cc[0] = bv0; cc[1] = bv1; cc[2] = bv0; cc[3] = bv1;
            }
        }

        // ---- pass A: acc[t] += Wih . h_prev[t] (no barriers needed) ----
        if (l == 0){
            // single K=16 step from x tiles (scalar LDS; tiny)
            uint32_t bh[8], bl[8];
            #pragma unroll
            for (int nf = 0; nf < 4; nf++){
                int jw = (n0 + nf*8 + g)*HPW + c;
                bh[nf*2]   = whW[jw]; bh[nf*2+1] = whW[jw + 4];
                bl[nf*2]   = wlW[jw]; bl[nf*2+1] = wlW[jw + 4];
            }
            #pragma unroll
            for (int t = 0; t < 4; t++){
                const uint32_t* xh = (const uint32_t*)(smem + OFF_X + t*X_PAIR);
                const uint32_t* xl = xh + 512;
                int rw = (m0 + g)*8 + c;
                uint32_t ah0 = xh[rw], ah1 = xh[rw + 64];
                uint32_t ah2 = xh[rw + 4], ah3 = xh[rw + 68];
                uint32_t al0 = xl[rw], al1 = xl[rw + 64];
                uint32_t al2 = xl[rw + 4], al3 = xl[rw + 68];
                float* ct = &acc[t*16];
                #pragma unroll
                for (int nf = 0; nf < 4; nf++)
                    mma16816(ct + nf*4, ah0,ah1,ah2,ah3, bh[nf*2], bh[nf*2+1]);
                #pragma unroll
                for (int nf = 0; nf < 4; nf++)
                    mma16816(ct + nf*4, ah0,ah1,ah2,ah3, bl[nf*2], bl[nf*2+1]);
                #pragma unroll
                for (int nf = 0; nf < 4; nf++)
                    mma16816(ct + nf*4, al0,al1,al2,al3, bh[nf*2], bh[nf*2+1]);
            }
        } else {
            #pragma unroll 1
            for (int kk = 0; kk < 8; kk++){
                uint32_t kb = kk * 32;       // 16 bf16 = 32 bytes per k-chunk
                uint32_t bh[8], bl[8];
                ldm4(bh,     whAddr + bOff0 + kb);
                ldm4(bh + 4, whAddr + bOff1 + kb);
                ldm4(bl,     wlAddr + bOff0 + kb);
                ldm4(bl + 4, wlAddr + bOff1 + kb);
                #pragma unroll
                for (int t = 0; t < 4; t++){
                    uint32_t hAddr = sb + OFF_H + t*H_PAIR + aOff + kb;
                    uint32_t ah[4], al[4];
                    ldm4(ah, hAddr);
                    ldm4(al, hAddr + H_TILE_BYTES);
                    float* ct = &acc[t*16];
                    #pragma unroll
                    for (int nf = 0; nf < 4; nf++)
                        mma16816(ct + nf*4, ah[0],ah[1],ah[2],ah[3], bh[nf*2], bh[nf*2+1]);
                    #pragma unroll
                    for (int nf = 0; nf < 4; nf++)
                        mma16816(ct + nf*4, ah[0],ah[1],ah[2],ah[3], bl[nf*2], bl[nf*2+1]);
                    #pragma unroll
                    for (int nf = 0; nf < 4; nf++)
                        mma16816(ct + nf*4, al[0],al[1],al[2],al[3], bh[nf*2], bh[nf*2+1]);
                }
            }
        }

        // ---- swap W region to W_hh(l); wait deferred into the t-loop ----
        __syncthreads();                     // pass-A reads of Wih done
        copyW_async(2*l + 1, sb + OFF_W, tid);

        // ---- pass B: sequential timesteps; 128-thread group barriers ----
        // t=0 epilogue (reads no W) runs under the Whh copy; the wait+sync
        // happens at the top of t==1, before the first chain touches W.
        #pragma unroll
        for (int t = 0; t < 4; t++){
            if (t > 0){
                if (t == 1){ CP_ASYNC_WAIT(); __syncthreads(); }  // Whh ready
                float* ct = &acc[t*16];
                uint32_t hBase = sb + OFF_H + (t-1)*H_PAIR;
                #pragma unroll 1
                for (int kk = 0; kk < 8; kk++){
                    uint32_t kb = kk * 32;
                    uint32_t bh[8], bl[8], ah[4], al[4];
                    ldm4(bh,     whAddr + bOff0 + kb);
                    ldm4(bh + 4, whAddr + bOff1 + kb);
                    ldm4(bl,     wlAddr + bOff0 + kb);
                    ldm4(bl + 4, wlAddr + bOff1 + kb);
                    ldm4(ah, hBase + aOff + kb);
                    ldm4(al, hBase + aOff + kb + H_TILE_BYTES);
                    #pragma unroll
                    for (int nf = 0; nf < 4; nf++)
                        mma16816(ct + nf*4, ah[0],ah[1],ah[2],ah[3], bh[nf*2], bh[nf*2+1]);
                    #pragma unroll
                    for (int nf = 0; nf < 4; nf++)
                        mma16816(ct + nf*4, ah[0],ah[1],ah[2],ah[3], bl[nf*2], bl[nf*2+1]);
                    #pragma unroll
                    for (int nf = 0; nf < 4; nf++)
                        mma16816(ct + nf*4, al[0],al[1],al[2],al[3], bh[nf*2], bh[nf*2+1]);
                }
            }
            // epilogue: h_t = tanh(acc[t]); split; store (in-place)
            uint32_t* hh = (uint32_t*)(smem + OFF_H + t*H_PAIR);
            epi_store(&acc[t*16], hh, hh + (H_TILE_BYTES >> 2), baseW);
            if (t < 3) GROUP_BAR(grp);       // h[t] visible within this batch group
            // t==3: next layer-top __syncthreads (or head's) provides ordering
        }
    }

    __syncthreads();                         // all groups' h[3] complete

    // ---- head: out[b] = dot(h3[b], wfc) + bfc ----
    if (tid < 256){
        int b = tid >> 2, q = tid & 3;
        const uint32_t* hh = (const uint32_t*)(smem + OFF_H + 3*H_PAIR);
        const uint32_t* hl = hh + (H_TILE_BYTES >> 2);
        float s = 0.0f;
        #pragma unroll
        for (int w = 0; w < 16; w++){
            int widx = b*HPW + q*16 + w;
            uint32_t uh = hh[widx], ul = hl[widx];
            __nv_bfloat162 vh = *(__nv_bfloat162*)&uh;
            __nv_bfloat162 vl = *(__nv_bfloat162*)&ul;
            int j = q*32 + 2*w;
            s = fmaf(__bfloat162float(vh.x) + __bfloat162float(vl.x), wfc[j],   s);
            s = fmaf(__bfloat162float(vh.y) + __bfloat162float(vl.y), wfc[j+1], s);
        }
        ((float*)(smem + OFF_SPART))[tid] = s;
    }
    __syncthreads();
    if (tid < 64){
        const float* sp = (const float*)(smem + OFF_SPART);
        long long gb = baseb + tid;
        if (gb < Btot)
            out[gb] = sp[tid*4] + sp[tid*4+1] + sp[tid*4+2] + sp[tid*4+3] + bfc[0];
    }
}

// ============================================================================
extern "C" void kernel_launch(void* const* d_in, const int* in_sizes, int n_in,
                              void* d_out, int out_size)
{
    const float* x    = (const float*)d_in[0];
    const float* Wih0 = (const float*)d_in[1];
    const float* Whh0 = (const float*)d_in[2];
    const float* bih0 = (const float*)d_in[3];
    const float* bhh0 = (const float*)d_in[4];
    const float* WihS = (const float*)d_in[5];
    const float* WhhS = (const float*)d_in[6];
    const float* bihS = (const float*)d_in[7];
    const float* bhhS = (const float*)d_in[8];
    const float* Wfc  = (const float*)d_in[9];
    const float* bfc  = (const float*)d_in[10];
    float* out = (float*)d_out;

    int Btot = in_sizes[0] / 20;
    int grid = (Btot + MB - 1) / MB;

    cudaFuncSetAttribute(rnn_mma,
                         cudaFuncAttributeMaxDynamicSharedMemorySize, SMEM_BYTES);

    prep_weights<<<10, 256>>>(Wih0, Whh0, WihS, WhhS);
    rnn_mma<<<grid, NT, SMEM_BYTES>>>(x, bih0, bhh0, bihS, bhhS,
                                      Wfc, bfc, out, Btot);
}